// round 11
// baseline (speedup 1.0000x reference)
#include <cuda_runtime.h>
#include <cuda_fp16.h>
#include <cstdint>

static constexpr int E = 64;
static constexpr int IN_DIM = 512;
static constexpr int NCLS = 10;

#define SWZ(o) ((o) ^ (((o) >> 3) & 0x70))

__device__ __forceinline__ uint32_t packh2(float a, float b) {
    __half2 h = __floats2half2_rn(a, b);
    return *reinterpret_cast<uint32_t*>(&h);
}
__device__ __forceinline__ __half2 u2h(uint32_t u) { return *reinterpret_cast<__half2*>(&u); }
__device__ __forceinline__ uint32_t h2u(__half2 h) { return *reinterpret_cast<uint32_t*>(&h); }
__device__ __forceinline__ uint32_t hfma2u(uint32_t a, uint32_t b, uint32_t c) {
    return h2u(__hfma2(u2h(a), u2h(b), u2h(c)));
}
__device__ __forceinline__ uint32_t hmax0(uint32_t a) {
    __half2 z = __half2half2(__ushort_as_half(0));
    return h2u(__hmax2(u2h(a), z));
}
__device__ __forceinline__ float2 h2f2(uint32_t u) { return __half22float2(u2h(u)); }

// fp32-accumulate legacy mma — x-GEMM only (K=512)
__device__ __forceinline__ void mma16816_f32(float d[4], const uint32_t a[4],
                                             uint32_t b0, uint32_t b1) {
    asm volatile(
        "mma.sync.aligned.m16n8k16.row.col.f32.f16.f16.f32 "
        "{%0,%1,%2,%3}, {%4,%5,%6,%7}, {%8,%9}, {%0,%1,%2,%3};\n"
        : "+f"(d[0]), "+f"(d[1]), "+f"(d[2]), "+f"(d[3])
        : "r"(a[0]), "r"(a[1]), "r"(a[2]), "r"(a[3]), "r"(b0), "r"(b1));
}
// fp16-accumulate legacy mma — in-loop workhorse
__device__ __forceinline__ void mma16816_f16(uint32_t d[2], const uint32_t a[4],
                                             uint32_t b0, uint32_t b1) {
    asm volatile(
        "mma.sync.aligned.m16n8k16.row.col.f16.f16.f16.f16 "
        "{%0,%1}, {%2,%3,%4,%5}, {%6,%7}, {%0,%1};\n"
        : "+r"(d[0]), "+r"(d[1])
        : "r"(a[0]), "r"(a[1]), "r"(a[2]), "r"(a[3]), "r"(b0), "r"(b1));
}
__device__ __forceinline__ void mma16816_f16_c0(uint32_t d[2], const uint32_t a[4],
                                                uint32_t b0, uint32_t b1) {
    uint32_t zero = 0;
    asm volatile(
        "mma.sync.aligned.m16n8k16.row.col.f16.f16.f16.f16 "
        "{%0,%1}, {%2,%3,%4,%5}, {%6,%7}, {%8,%8};\n"
        : "=r"(d[0]), "=r"(d[1])
        : "r"(a[0]), "r"(a[1]), "r"(a[2]), "r"(a[3]), "r"(b0), "r"(b1), "r"(zero));
}

// ============================================================================
// Device scratch
// ============================================================================
__device__ __align__(16) float g_WcP[4 * E * IN_DIM];   // 4-way e-split partials
__device__ __align__(16) uint2 g_WcF[32 * 8 * 32];      // B-frags of Wc (K=512)
__device__ __align__(16) uint4 g_W1zF4[512];            // B-frags of W1z, q-paired
__device__ __align__(16) uint4 g_W2F4[512];             // B-frags of 0.1*W2
__device__ __align__(16) uint32_t g_w1tF[8 * 32];       // half2 frags of W1[:,128]
__device__ __align__(16) float2 g_bias1F[8 * 32];       // b1 + W1f@b_feat + W1z@b2
__device__ __align__(16) float g_logit_off[16];         // b2 @ class_emb^T

// ============================================================================
// Prep 1: 4-way e-split partials of Wc = W1[:, :64] @ W_feat (fast, 131K thr)
// ============================================================================
__global__ void prep1_kernel(const float* __restrict__ W_feat,
                             const float* __restrict__ W1) {
    int idx = blockIdx.x * 256 + threadIdx.x;
    if (idx >= 4 * E * IN_DIM) return;
    int p = idx >> 15;
    int r = idx & 32767;
    int j = r >> 9, k = r & 511;
    int e0 = p * 16;
    float acc = 0.f;
    #pragma unroll
    for (int e = 0; e < 16; e++)
        acc = fmaf(W1[j * 129 + e0 + e], W_feat[(e0 + e) * IN_DIM + k], acc);
    g_WcP[idx] = acc;
}

// ============================================================================
// Prep 2: fragments + folded constants
// ============================================================================
__global__ void prep2_kernel(const float* __restrict__ b_feat,
                             const float* __restrict__ W1,
                             const float* __restrict__ b1,
                             const float* __restrict__ W2,
                             const float* __restrict__ b2,
                             const float* __restrict__ class_emb) {
    int idx = blockIdx.x * 256 + threadIdx.x;
    if (idx < 8192) {                                   // WcF from partial sums
        int L = idx & 31, j = (idx >> 5) & 7, q = idx >> 8;
        int n = 8 * j + (L >> 2), k0 = 16 * q + 2 * (L & 3);
        float w[4];
        #pragma unroll
        for (int s = 0; s < 4; s++) {
            int k = k0 + (s & 1) + (s >> 1) * 8;
            float acc = 0.f;
            #pragma unroll
            for (int p = 0; p < 4; p++) acc += g_WcP[p * 32768 + n * IN_DIM + k];
            w[s] = acc;
        }
        g_WcF[idx] = make_uint2(packh2(w[0], w[1]), packh2(w[2], w[3]));
    } else if (idx < 8704) {                            // W1zF4
        int f = idx - 8192;
        int L = f & 31, qp = (f >> 5) & 1, j = f >> 6;
        int n = 8 * j + (L >> 2);
        const float* w = W1 + n * 129 + 64;
        int ka = 32 * qp + 2 * (L & 3), kb = ka + 16;
        g_W1zF4[f] = make_uint4(packh2(w[ka], w[ka + 1]), packh2(w[ka + 8], w[ka + 9]),
                                packh2(w[kb], w[kb + 1]), packh2(w[kb + 8], w[kb + 9]));
    } else if (idx < 9216) {                            // W2F4 (0.1*W2)
        int f = idx - 8704;
        int L = f & 31, qp = (f >> 5) & 1, j = f >> 6;
        int n = 8 * j + (L >> 2);
        const float* w = W2 + n * E;
        int ka = 32 * qp + 2 * (L & 3), kb = ka + 16;
        g_W2F4[f] = make_uint4(
            packh2(0.1f * w[ka], 0.1f * w[ka + 1]), packh2(0.1f * w[ka + 8], 0.1f * w[ka + 9]),
            packh2(0.1f * w[kb], 0.1f * w[kb + 1]), packh2(0.1f * w[kb + 8], 0.1f * w[kb + 9]));
    } else if (idx < 9472) {                            // w1tF
        int f = idx - 9216;
        int L = f & 31, j = f >> 5;
        int n0 = 8 * j + 2 * (L & 3);
        g_w1tF[f] = packh2(W1[n0 * 129 + 128], W1[(n0 + 1) * 129 + 128]);
    } else if (idx < 9728) {                            // bias1F (+ W1z@b2 fold)
        int f = idx - 9472;
        int L = f & 31, j = f >> 5;
        int n0 = 8 * j + 2 * (L & 3);
        float2 bb;
        float* bp = &bb.x;
        #pragma unroll
        for (int s = 0; s < 2; s++) {
            int n = n0 + s;
            float acc = b1[n];
            for (int e = 0; e < E; e++) {
                acc = fmaf(W1[n * 129 + e], b_feat[e], acc);
                acc = fmaf(W1[n * 129 + 64 + e], b2[e], acc);
            }
            bp[s] = acc;
        }
        g_bias1F[f] = bb;
    } else if (idx < 9744) {                            // logit offsets
        int cls = idx - 9728;
        float acc = 0.f;
        if (cls < NCLS)
            for (int n = 0; n < E; n++) acc = fmaf(b2[n], class_emb[cls * E + n], acc);
        g_logit_off[cls] = acc;
    }
}

// ============================================================================
// Main kernel: ONE warp per CTA, ONE 32-row tile. grid = Bn/32 = 2048 CTAs,
// 8 co-resident CTAs/SM -> 2 warps/SMSP sustained (the saturating rate) with
// fine-grained work-steal -> no wave-quantization tail.
// ============================================================================
__global__ __launch_bounds__(32, 8)
void iter_kernel(const float* __restrict__ x,
                 const float* __restrict__ z0,
                 const float* __restrict__ b2,
                 const float* __restrict__ class_emb,
                 const int* __restrict__ Tptr,
                 float* __restrict__ out,
                 int Bn) {
    __shared__ __align__(16) uint4 sW1z4[512];          // 8 KB
    __shared__ __align__(16) uint4 sW24[512];           // 8 KB
    __shared__ __align__(128) char sX[4096];            // 32 rows x 128B fp16
    __shared__ float sCE[NCLS * E];
    __shared__ float sOff[16];

    const int lane = threadIdx.x;
    const int g    = lane >> 2;
    const int t4   = lane & 3;
    const int rowbase = blockIdx.x * 32;

    // ---- per-CTA weight/constant loads (32 lanes) ----
    for (int i = lane; i < 512; i += 32) { sW1z4[i] = g_W1zF4[i]; sW24[i] = g_W2F4[i]; }
    for (int i = lane; i < NCLS * E; i += 32) sCE[i] = class_emb[i];
    if (lane < 16) sOff[lane] = g_logit_off[lane];

    uint32_t w1t2[8];
    #pragma unroll
    for (int j = 0; j < 8; j++) w1t2[j] = g_w1tF[j * 32 + lane];

    int T = Tptr ? Tptr[0] : 40;
    if (T <= 0 || T > 1000000) {
        float tf = __int_as_float(T);
        T = (tf > 0.5f && tf < 1.0e6f) ? (int)tf : 40;
    }
    const float invT = 1.0f / (float)T;

    // ---------------- u = x @ Wc^T (K=512, fp32 acc) ----------------
    float u[2][8][4];
    #pragma unroll
    for (int i = 0; i < 2; i++)
        #pragma unroll
        for (int j = 0; j < 8; j++)
            #pragma unroll
            for (int c = 0; c < 4; c++) u[i][j][c] = 0.f;

    for (int ch = 0; ch < 8; ch++) {
        __syncwarp();
        // stage 32 rows x 64 cols fp32 -> fp16 swizzled (256 uint4 stores)
        for (int s = lane; s < 256; s += 32) {
            int r = s >> 3, cq = s & 7;
            int rr = rowbase + r; if (rr >= Bn) rr = Bn - 1;
            const float4* p = (const float4*)(x + (size_t)rr * IN_DIM + ch * 64 + cq * 8);
            float4 v0 = p[0], v1 = p[1];
            uint4 pk;
            pk.x = packh2(v0.x, v0.y); pk.y = packh2(v0.z, v0.w);
            pk.z = packh2(v1.x, v1.y); pk.w = packh2(v1.z, v1.w);
            *(uint4*)(sX + SWZ(r * 128 + cq * 16)) = pk;
        }
        __syncwarp();
        #pragma unroll
        for (int q = 0; q < 4; q++) {
            uint32_t a[2][4];
            #pragma unroll
            for (int i = 0; i < 2; i++) {
                int rb0 = (i * 16 + g) * 128;
                int rb1 = rb0 + 8 * 128;
                int cb  = q * 32 + t4 * 4;
                a[i][0] = *(const uint32_t*)(sX + SWZ(rb0 + cb));
                a[i][1] = *(const uint32_t*)(sX + SWZ(rb1 + cb));
                a[i][2] = *(const uint32_t*)(sX + SWZ(rb0 + cb + 16));
                a[i][3] = *(const uint32_t*)(sX + SWZ(rb1 + cb + 16));
            }
            #pragma unroll
            for (int j = 0; j < 8; j++) {
                uint2 b = g_WcF[((ch * 4 + q) * 8 + j) * 32 + lane];
                mma16816_f32(u[0][j], a[0], b.x, b.y);
                mma16816_f32(u[1][j], a[1], b.x, b.y);
            }
        }
    }

    // ---- fold bias1 into u, keep as fp16 (GEMM1 C-init base) ----
    uint32_t uh[2][8][2];
    #pragma unroll
    for (int j = 0; j < 8; j++) {
        float2 bb = g_bias1F[j * 32 + lane];
        #pragma unroll
        for (int i = 0; i < 2; i++) {
            uh[i][j][0] = packh2(u[i][j][0] + bb.x, u[i][j][1] + bb.y);
            uh[i][j][1] = packh2(u[i][j][2] + bb.x, u[i][j][3] + bb.y);
        }
    }

    // ---- y0 = z0 - b2 (fp32 master) ----
    float y[2][8][4];
    #pragma unroll
    for (int i = 0; i < 2; i++) {
        int r0 = rowbase + i * 16 + g; if (r0 >= Bn) r0 = Bn - 1;
        int r1 = r0 + 8;               if (r1 >= Bn) r1 = Bn - 1;
        #pragma unroll
        for (int j = 0; j < 8; j++) {
            float2 bv = *(const float2*)(b2 + 8 * j + 2 * t4);
            float2 v0 = *(const float2*)(z0 + (size_t)r0 * E + 8 * j + 2 * t4);
            float2 v1 = *(const float2*)(z0 + (size_t)r1 * E + 8 * j + 2 * t4);
            y[i][j][0] = v0.x - bv.x; y[i][j][1] = v0.y - bv.y;
            y[i][j][2] = v1.x - bv.x; y[i][j][3] = v1.y - bv.y;
        }
    }

    // ---------------- recurrence (fp16-acc MMAs) ----------------
    for (int step = 0; step < T; step++) {
        const float tv = (float)step * invT;
        const uint32_t tvu = packh2(tv, tv);

        uint32_t a[2][4][4];
        #pragma unroll
        for (int i = 0; i < 2; i++)
            #pragma unroll
            for (int q = 0; q < 4; q++) {
                a[i][q][0] = packh2(y[i][2 * q][0],     y[i][2 * q][1]);
                a[i][q][1] = packh2(y[i][2 * q][2],     y[i][2 * q][3]);
                a[i][q][2] = packh2(y[i][2 * q + 1][0], y[i][2 * q + 1][1]);
                a[i][q][3] = packh2(y[i][2 * q + 1][2], y[i][2 * q + 1][3]);
            }

        // GEMM1 (fp16 acc): dh = (u + t*w1t) + y @ W1z^T
        uint32_t dh[2][8][2];
        #pragma unroll
        for (int i = 0; i < 2; i++)
            #pragma unroll
            for (int j = 0; j < 8; j++) {
                dh[i][j][0] = hfma2u(tvu, w1t2[j], uh[i][j][0]);
                dh[i][j][1] = hfma2u(tvu, w1t2[j], uh[i][j][1]);
            }
        #pragma unroll
        for (int qp = 0; qp < 2; qp++)
            #pragma unroll
            for (int j = 0; j < 8; j++) {
                uint4 bf = sW1z4[(j * 2 + qp) * 32 + lane];
                mma16816_f16(dh[0][j], a[0][2 * qp],     bf.x, bf.y);
                mma16816_f16(dh[0][j], a[0][2 * qp + 1], bf.z, bf.w);
                mma16816_f16(dh[1][j], a[1][2 * qp],     bf.x, bf.y);
                mma16816_f16(dh[1][j], a[1][2 * qp + 1], bf.z, bf.w);
            }

        // h = relu(dh): fp16 D-frags ARE the GEMM2 A-frags
        uint32_t ha[2][4][4];
        #pragma unroll
        for (int i = 0; i < 2; i++)
            #pragma unroll
            for (int q = 0; q < 4; q++) {
                ha[i][q][0] = hmax0(dh[i][2 * q][0]);
                ha[i][q][1] = hmax0(dh[i][2 * q][1]);
                ha[i][q][2] = hmax0(dh[i][2 * q + 1][0]);
                ha[i][q][3] = hmax0(dh[i][2 * q + 1][1]);
            }

        // GEMM2 (fp16 acc): delta = h @ (0.1*W2)^T
        uint32_t dl[2][8][2];
        #pragma unroll
        for (int j = 0; j < 8; j++) {
            uint4 bf0 = sW24[(j * 2) * 32 + lane];
            uint4 bf1 = sW24[(j * 2 + 1) * 32 + lane];
            #pragma unroll
            for (int i = 0; i < 2; i++) {
                mma16816_f16_c0(dl[i][j], ha[i][0], bf0.x, bf0.y);
                mma16816_f16(dl[i][j], ha[i][1], bf0.z, bf0.w);
                mma16816_f16(dl[i][j], ha[i][2], bf1.x, bf1.y);
                mma16816_f16(dl[i][j], ha[i][3], bf1.z, bf1.w);
            }
        }

        // y = 0.9*y + float(delta)
        #pragma unroll
        for (int i = 0; i < 2; i++)
            #pragma unroll
            for (int j = 0; j < 8; j++) {
                float2 lo = h2f2(dl[i][j][0]);
                float2 hi = h2f2(dl[i][j][1]);
                y[i][j][0] = fmaf(0.9f, y[i][j][0], lo.x);
                y[i][j][1] = fmaf(0.9f, y[i][j][1], lo.y);
                y[i][j][2] = fmaf(0.9f, y[i][j][2], hi.x);
                y[i][j][3] = fmaf(0.9f, y[i][j][3], hi.y);
            }
    }

    // ---------------- logits = y @ CE^T + off ----------------
    #pragma unroll 2
    for (int cls = 0; cls < NCLS; cls++) {
        float acc0 = 0.f, acc1 = 0.f, acc2 = 0.f, acc3 = 0.f;
        #pragma unroll
        for (int j = 0; j < 8; j++) {
            float2 ce = *(const float2*)(&sCE[cls * E + 8 * j + 2 * t4]);
            acc0 = fmaf(y[0][j][0], ce.x, fmaf(y[0][j][1], ce.y, acc0));
            acc1 = fmaf(y[0][j][2], ce.x, fmaf(y[0][j][3], ce.y, acc1));
            acc2 = fmaf(y[1][j][0], ce.x, fmaf(y[1][j][1], ce.y, acc2));
            acc3 = fmaf(y[1][j][2], ce.x, fmaf(y[1][j][3], ce.y, acc3));
        }
        acc0 += __shfl_xor_sync(0xffffffffu, acc0, 1);
        acc0 += __shfl_xor_sync(0xffffffffu, acc0, 2);
        acc1 += __shfl_xor_sync(0xffffffffu, acc1, 1);
        acc1 += __shfl_xor_sync(0xffffffffu, acc1, 2);
        acc2 += __shfl_xor_sync(0xffffffffu, acc2, 1);
        acc2 += __shfl_xor_sync(0xffffffffu, acc2, 2);
        acc3 += __shfl_xor_sync(0xffffffffu, acc3, 1);
        acc3 += __shfl_xor_sync(0xffffffffu, acc3, 2);
        if (t4 == 0) {
            float off = sOff[cls];
            int r0 = rowbase + g;
            if (r0 < Bn)      out[(size_t)r0 * NCLS + cls] = acc0 + off;
            if (r0 + 8 < Bn)  out[(size_t)(r0 + 8) * NCLS + cls] = acc1 + off;
            if (r0 + 16 < Bn) out[(size_t)(r0 + 16) * NCLS + cls] = acc2 + off;
            if (r0 + 24 < Bn) out[(size_t)(r0 + 24) * NCLS + cls] = acc3 + off;
        }
    }
}

// ============================================================================
// Launch
// ============================================================================
extern "C" void kernel_launch(void* const* d_in, const int* in_sizes, int n_in,
                              void* d_out, int out_size) {
    const float* x         = (const float*)d_in[0];
    const float* z0        = (const float*)d_in[1];
    const float* W_feat    = (const float*)d_in[2];
    const float* b_feat    = (const float*)d_in[3];
    const float* W1        = (const float*)d_in[4];
    const float* b1        = (const float*)d_in[5];
    const float* W2        = (const float*)d_in[6];
    const float* b2        = (const float*)d_in[7];
    const float* class_emb = (const float*)d_in[8];
    const int*   T_steps   = (n_in > 9) ? (const int*)d_in[9] : nullptr;
    float* out = (float*)d_out;

    int Bn = in_sizes[1] / E;

    prep1_kernel<<<512, 256>>>(W_feat, W1);
    prep2_kernel<<<(9744 + 255) / 256, 256>>>(b_feat, W1, b1, W2, b2, class_emb);

    int grid = (Bn + 31) / 32;
    iter_kernel<<<grid, 32>>>(x, z0, b2, class_emb, T_steps, out, Bn);
}

// round 12
// speedup vs baseline: 1.0612x; 1.0612x over previous
#include <cuda_runtime.h>
#include <cuda_fp16.h>
#include <cstdint>

// ============================================================================
// Portable tensor-core path: mma.sync.m16n8k16 (f16 in, f32 accum).
// The harness compiles for plain sm_100 (no 'a' suffix) -> no tcgen05.
// Proven-best iter kernel (163.9us, rel_err 2.05e-4) at the legacy-HMMA
// issue floor (11.53M MMAs x rt16 / 592 SMSP @ 1.9GHz = 163.7us).
// This round: prep1 8-way K-split (latency-bound -> more parallelism).
// ============================================================================

static constexpr int E = 64;
static constexpr int IN_DIM = 512;
static constexpr int NCLS = 10;

#define SWZ(o) ((o) ^ (((o) >> 3) & 0x70))

__device__ __forceinline__ uint32_t packh2(float a, float b) {
    __half2 h = __floats2half2_rn(a, b);
    return *reinterpret_cast<uint32_t*>(&h);
}

__device__ __forceinline__ void mma16816(float d[4], const uint32_t a[4], uint2 b) {
    asm volatile(
        "mma.sync.aligned.m16n8k16.row.col.f32.f16.f16.f32 "
        "{%0,%1,%2,%3}, {%4,%5,%6,%7}, {%8,%9}, {%0,%1,%2,%3};\n"
        : "+f"(d[0]), "+f"(d[1]), "+f"(d[2]), "+f"(d[3])
        : "r"(a[0]), "r"(a[1]), "r"(a[2]), "r"(a[3]), "r"(b.x), "r"(b.y));
}

// ============================================================================
// Device scratch (no dynamic allocation allowed)
// ============================================================================
__device__ __align__(16) float g_WcP[8 * E * IN_DIM];   // 8-way e-split partials
__device__ __align__(16) uint2 g_W1zF[8 * 4 * 32];      // B-frags of W1[:, 64:128]
__device__ __align__(16) uint2 g_W2F[8 * 4 * 32];       // B-frags of 0.1*W2
__device__ __align__(16) uint2 g_WcF[32 * 8 * 32];      // B-frags of Wc (K=512)
__device__ __align__(16) float g_bias1[E];              // b1 + W1[:, :64] @ b_feat
__device__ __align__(16) float g_w1t[E];                // W1[:, 128]

// ============================================================================
// Prep 1: 8-way e-split partials of Wc = W1[:, :64] @ W_feat  (262K threads)
// ============================================================================
__global__ void prep1_kernel(const float* __restrict__ W_feat,
                             const float* __restrict__ W1) {
    int idx = blockIdx.x * 256 + threadIdx.x;           // 262144 threads
    if (idx >= 8 * E * IN_DIM) return;
    int p = idx >> 15;                                  // e-octant 0..7
    int r = idx & 32767;
    int j = r >> 9, k = r & 511;
    int e0 = p * 8;
    float acc = 0.f;
    #pragma unroll
    for (int e = 0; e < 8; e++)
        acc = fmaf(W1[j * 129 + e0 + e], W_feat[(e0 + e) * IN_DIM + k], acc);
    g_WcP[idx] = acc;
}

// ============================================================================
// Prep 2: build per-lane B fragments + folded biases (R2/R10 layouts).
// B frag for m16n8k16.col: lane L (g=L>>2, t=L&3), n-tile j, k-chunk q:
//   b0 = {W[8j+g][16q+2t],   W[8j+g][16q+2t+1]}
//   b1 = {W[8j+g][16q+2t+8], W[8j+g][16q+2t+9]}
// ============================================================================
__global__ void prep2_kernel(const float* __restrict__ b_feat,
                             const float* __restrict__ W1,
                             const float* __restrict__ b1,
                             const float* __restrict__ W2) {
    int idx = blockIdx.x * 256 + threadIdx.x;
    if (idx < 8192) {                                   // WcF from partial sums
        int L = idx & 31, j = (idx >> 5) & 7, q = idx >> 8;
        int n = 8 * j + (L >> 2), k0 = 16 * q + 2 * (L & 3);
        float w[4];
        #pragma unroll
        for (int s = 0; s < 4; s++) {
            int k = k0 + (s & 1) + (s >> 1) * 8;        // k0, k0+1, k0+8, k0+9
            float acc = 0.f;
            #pragma unroll
            for (int p = 0; p < 8; p++) acc += g_WcP[p * 32768 + n * IN_DIM + k];
            w[s] = acc;
        }
        g_WcF[idx] = make_uint2(packh2(w[0], w[1]), packh2(w[2], w[3]));
    } else if (idx < 9216) {                            // W1zF
        int f = idx - 8192;
        int L = f & 31, q = (f >> 5) & 3, j = f >> 7;
        int n = 8 * j + (L >> 2), k0 = 16 * q + 2 * (L & 3);
        const float* w = W1 + n * 129 + 64;
        g_W1zF[f] = make_uint2(packh2(w[k0], w[k0 + 1]),
                               packh2(w[k0 + 8], w[k0 + 9]));
    } else if (idx < 10240) {                           // W2F (pre-scaled by 0.1)
        int f = idx - 9216;
        int L = f & 31, q = (f >> 5) & 3, j = f >> 7;
        int n = 8 * j + (L >> 2), k0 = 16 * q + 2 * (L & 3);
        const float* w = W2 + n * E;
        g_W2F[f] = make_uint2(packh2(0.1f * w[k0], 0.1f * w[k0 + 1]),
                              packh2(0.1f * w[k0 + 8], 0.1f * w[k0 + 9]));
    } else if (idx < 10240 + E) {                       // bias1, w1t
        int n = idx - 10240;
        float acc = b1[n];
        for (int e = 0; e < E; e++) acc += W1[n * 129 + e] * b_feat[e];
        g_bias1[n] = acc;
        g_w1t[n] = W1[n * 129 + 128];
    }
}

// ============================================================================
// Main kernel: 128 threads = 4 warps, 32 rows/warp. Register-resident
// recurrence, no in-loop synchronization of any kind. (Proven 163.9us.)
// ============================================================================
__global__ __launch_bounds__(128, 2)
void iter_kernel(const float* __restrict__ x,
                 const float* __restrict__ z0,
                 const float* __restrict__ b2,
                 const float* __restrict__ class_emb,
                 const int* __restrict__ Tptr,
                 float* __restrict__ out,
                 int Bn) {
    __shared__ __align__(16) uint2 sW1z[1024];          // 8 KB
    __shared__ __align__(16) uint2 sW2[1024];           // 8 KB
    __shared__ float sBias1[E], sW1t[E], sB2s[E];
    __shared__ float sCE[NCLS * E];
    __shared__ __align__(128) char sX[128 * 128];       // 16 KB fp16, swizzled

    const int tid  = threadIdx.x;
    const int lane = tid & 31;
    const int g    = lane >> 2;
    const int t4   = lane & 3;
    const int warp = tid >> 5;
    const int ctabase = blockIdx.x * 128;
    const int rowbase = ctabase + warp * 32;

    // ---- cooperative weight/constant loads ----
    for (int i = tid; i < 1024; i += 128) { sW1z[i] = g_W1zF[i]; sW2[i] = g_W2F[i]; }
    if (tid < E) {
        sBias1[tid] = g_bias1[tid];
        sW1t[tid]   = g_w1t[tid];
        sB2s[tid]   = 0.1f * b2[tid];
    }
    for (int i = tid; i < NCLS * E; i += 128) sCE[i] = class_emb[i];

    // ======================= u = x @ Wc^T  (K = 512) =======================
    float u[2][8][4];
    #pragma unroll
    for (int i = 0; i < 2; i++)
        #pragma unroll
        for (int j = 0; j < 8; j++)
            #pragma unroll
            for (int c = 0; c < 4; c++) u[i][j][c] = 0.f;

    for (int ch = 0; ch < 8; ch++) {
        __syncthreads();   // protect sX reuse (also covers initial weight loads)
        // stage 128 rows x 64 cols fp32 -> fp16, swizzled
        for (int s = tid; s < 1024; s += 128) {
            int r = s >> 3, cq = s & 7;
            int rr = ctabase + r; if (rr >= Bn) rr = Bn - 1;
            const float4* p = (const float4*)(x + (size_t)rr * IN_DIM + ch * 64 + cq * 8);
            float4 v0 = p[0], v1 = p[1];
            uint4 pk;
            pk.x = packh2(v0.x, v0.y); pk.y = packh2(v0.z, v0.w);
            pk.z = packh2(v1.x, v1.y); pk.w = packh2(v1.z, v1.w);
            *(uint4*)(sX + SWZ(r * 128 + cq * 16)) = pk;
        }
        __syncthreads();
        #pragma unroll
        for (int q = 0; q < 4; q++) {
            uint32_t a[2][4];
            #pragma unroll
            for (int i = 0; i < 2; i++) {
                int rb0 = (warp * 32 + i * 16 + g) * 128;
                int rb1 = rb0 + 8 * 128;
                int cb  = q * 32 + t4 * 4;
                a[i][0] = *(const uint32_t*)(sX + SWZ(rb0 + cb));
                a[i][1] = *(const uint32_t*)(sX + SWZ(rb1 + cb));
                a[i][2] = *(const uint32_t*)(sX + SWZ(rb0 + cb + 16));
                a[i][3] = *(const uint32_t*)(sX + SWZ(rb1 + cb + 16));
            }
            #pragma unroll
            for (int j = 0; j < 8; j++) {
                uint2 b = g_WcF[((ch * 4 + q) * 8 + j) * 32 + lane];
                mma16816(u[0][j], a[0], b);
                mma16816(u[1][j], a[1], b);
            }
        }
    }
    __syncthreads();

    // ---- fold bias1 into u, compress to half2 (frees 32 regs) ----
    uint32_t uh[2][8][2];
    #pragma unroll
    for (int j = 0; j < 8; j++) {
        float b0 = sBias1[8 * j + 2 * t4], b1v = sBias1[8 * j + 2 * t4 + 1];
        #pragma unroll
        for (int i = 0; i < 2; i++) {
            uh[i][j][0] = packh2(u[i][j][0] + b0, u[i][j][1] + b1v);
            uh[i][j][1] = packh2(u[i][j][2] + b0, u[i][j][3] + b1v);
        }
    }

    float w1tv[8][2], b2v[8][2];
    #pragma unroll
    for (int j = 0; j < 8; j++) {
        w1tv[j][0] = sW1t[8 * j + 2 * t4];  w1tv[j][1] = sW1t[8 * j + 2 * t4 + 1];
        b2v[j][0]  = sB2s[8 * j + 2 * t4];  b2v[j][1]  = sB2s[8 * j + 2 * t4 + 1];
    }

    // ---- z0 -> registers (D-fragment layout, fp32 master) ----
    float z[2][8][4];
    #pragma unroll
    for (int i = 0; i < 2; i++) {
        int r0 = rowbase + i * 16 + g; if (r0 >= Bn) r0 = Bn - 1;
        int r1 = r0 + 8;               if (r1 >= Bn) r1 = Bn - 1;
        #pragma unroll
        for (int j = 0; j < 8; j++) {
            float2 v0 = *(const float2*)(z0 + (size_t)r0 * E + 8 * j + 2 * t4);
            float2 v1 = *(const float2*)(z0 + (size_t)r1 * E + 8 * j + 2 * t4);
            z[i][j][0] = v0.x; z[i][j][1] = v0.y;
            z[i][j][2] = v1.x; z[i][j][3] = v1.y;
        }
    }

    // ---- T ----
    int T = Tptr ? Tptr[0] : 40;
    if (T <= 0 || T > 1000000) {
        float tf = __int_as_float(T);
        T = (tf > 0.5f && tf < 1.0e6f) ? (int)tf : 40;
    }
    const float invT = 1.0f / (float)T;

    // ======================= 40-step recurrence (registers only) ============
    for (int step = 0; step < T; step++) {
        const float tv = (float)step * invT;

        // ---- GEMM1: d = u + t*w1t + z @ W1z^T ----
        float d[2][8][4];
        #pragma unroll
        for (int i = 0; i < 2; i++)
            #pragma unroll
            for (int j = 0; j < 8; j++) {
                float2 lo = __half22float2(*reinterpret_cast<__half2*>(&uh[i][j][0]));
                float2 hi = __half22float2(*reinterpret_cast<__half2*>(&uh[i][j][1]));
                d[i][j][0] = fmaf(tv, w1tv[j][0], lo.x);
                d[i][j][1] = fmaf(tv, w1tv[j][1], lo.y);
                d[i][j][2] = fmaf(tv, w1tv[j][0], hi.x);
                d[i][j][3] = fmaf(tv, w1tv[j][1], hi.y);
            }
        #pragma unroll
        for (int q = 0; q < 4; q++) {
            uint32_t a[2][4];
            #pragma unroll
            for (int i = 0; i < 2; i++) {
                a[i][0] = packh2(z[i][2 * q][0],     z[i][2 * q][1]);
                a[i][1] = packh2(z[i][2 * q][2],     z[i][2 * q][3]);
                a[i][2] = packh2(z[i][2 * q + 1][0], z[i][2 * q + 1][1]);
                a[i][3] = packh2(z[i][2 * q + 1][2], z[i][2 * q + 1][3]);
            }
            #pragma unroll
            for (int j = 0; j < 8; j++) {
                uint2 b = sW1z[(j * 4 + q) * 32 + lane];
                mma16816(d[0][j], a[0], b);
                mma16816(d[1][j], a[1], b);
            }
        }

        // ---- h = relu(d), packed directly as A-fragments ----
        uint32_t ha[2][4][4];
        #pragma unroll
        for (int i = 0; i < 2; i++)
            #pragma unroll
            for (int q = 0; q < 4; q++) {
                ha[i][q][0] = packh2(fmaxf(d[i][2 * q][0], 0.f),     fmaxf(d[i][2 * q][1], 0.f));
                ha[i][q][1] = packh2(fmaxf(d[i][2 * q][2], 0.f),     fmaxf(d[i][2 * q][3], 0.f));
                ha[i][q][2] = packh2(fmaxf(d[i][2 * q + 1][0], 0.f), fmaxf(d[i][2 * q + 1][1], 0.f));
                ha[i][q][3] = packh2(fmaxf(d[i][2 * q + 1][2], 0.f), fmaxf(d[i][2 * q + 1][3], 0.f));
            }

        // ---- GEMM2: z = 0.9*z + 0.1*b2 + h @ (0.1*W2)^T  (z IS the accumulator)
        #pragma unroll
        for (int i = 0; i < 2; i++)
            #pragma unroll
            for (int j = 0; j < 8; j++) {
                z[i][j][0] = fmaf(0.9f, z[i][j][0], b2v[j][0]);
                z[i][j][1] = fmaf(0.9f, z[i][j][1], b2v[j][1]);
                z[i][j][2] = fmaf(0.9f, z[i][j][2], b2v[j][0]);
                z[i][j][3] = fmaf(0.9f, z[i][j][3], b2v[j][1]);
            }
        #pragma unroll
        for (int q = 0; q < 4; q++)
            #pragma unroll
            for (int j = 0; j < 8; j++) {
                uint2 b = sW2[(j * 4 + q) * 32 + lane];
                mma16816(z[0][j], ha[0][q], b);
                mma16816(z[1][j], ha[1][q], b);
            }
    }

    // ======================= logits = z @ class_emb^T =======================
    #pragma unroll 2
    for (int cls = 0; cls < NCLS; cls++) {
        float acc0 = 0.f, acc1 = 0.f, acc2 = 0.f, acc3 = 0.f;
        #pragma unroll
        for (int j = 0; j < 8; j++) {
            float2 ce = *(const float2*)(&sCE[cls * E + 8 * j + 2 * t4]);
            acc0 = fmaf(z[0][j][0], ce.x, fmaf(z[0][j][1], ce.y, acc0));
            acc1 = fmaf(z[0][j][2], ce.x, fmaf(z[0][j][3], ce.y, acc1));
            acc2 = fmaf(z[1][j][0], ce.x, fmaf(z[1][j][1], ce.y, acc2));
            acc3 = fmaf(z[1][j][2], ce.x, fmaf(z[1][j][3], ce.y, acc3));
        }
        acc0 += __shfl_xor_sync(0xffffffffu, acc0, 1);
        acc0 += __shfl_xor_sync(0xffffffffu, acc0, 2);
        acc1 += __shfl_xor_sync(0xffffffffu, acc1, 1);
        acc1 += __shfl_xor_sync(0xffffffffu, acc1, 2);
        acc2 += __shfl_xor_sync(0xffffffffu, acc2, 1);
        acc2 += __shfl_xor_sync(0xffffffffu, acc2, 2);
        acc3 += __shfl_xor_sync(0xffffffffu, acc3, 1);
        acc3 += __shfl_xor_sync(0xffffffffu, acc3, 2);
        if (t4 == 0) {
            int r0 = rowbase + g;
            if (r0 < Bn)      out[(size_t)r0 * NCLS + cls] = acc0;
            if (r0 + 8 < Bn)  out[(size_t)(r0 + 8) * NCLS + cls] = acc1;
            if (r0 + 16 < Bn) out[(size_t)(r0 + 16) * NCLS + cls] = acc2;
            if (r0 + 24 < Bn) out[(size_t)(r0 + 24) * NCLS + cls] = acc3;
        }
    }
}

// ============================================================================
// Launch
// ============================================================================
extern "C" void kernel_launch(void* const* d_in, const int* in_sizes, int n_in,
                              void* d_out, int out_size) {
    const float* x         = (const float*)d_in[0];
    const float* z0        = (const float*)d_in[1];
    const float* W_feat    = (const float*)d_in[2];
    const float* b_feat    = (const float*)d_in[3];
    const float* W1        = (const float*)d_in[4];
    const float* b1        = (const float*)d_in[5];
    const float* W2        = (const float*)d_in[6];
    const float* b2        = (const float*)d_in[7];
    const float* class_emb = (const float*)d_in[8];
    const int*   T_steps   = (n_in > 9) ? (const int*)d_in[9] : nullptr;
    float* out = (float*)d_out;

    int Bn = in_sizes[1] / E;   // z0 is [B, 64]

    prep1_kernel<<<1024, 256>>>(W_feat, W1);
    prep2_kernel<<<(10240 + E + 255) / 256, 256>>>(b_feat, W1, b1, W2);

    int grid = (Bn + 127) / 128;
    iter_kernel<<<grid, 128>>>(x, z0, b2, class_emb, T_steps, out, Bn);
}